// round 4
// baseline (speedup 1.0000x reference)
#include <cuda_runtime.h>

// ---------------------------------------------------------------------------
// SpMiddleFHD: subm3x3x3 conv 128->16 relu, subm 16->16 relu, strided (s=2,p=1)
// conv 16->32 scattered into dense (B,Do,Ho,Wo,32) with relu.
// B=2, Dz=41, Hy=400, Wx=352, N=40000, Do=21, Ho=200, Wo=176.
//
// Grid hash: idx+1 in uint16 (0 = empty). Device globals are zero-init at
// load; conv2 (after the last grid reader) clears the 40000 touched cells,
// preserving the all-zero invariant across graph replays.
//
// Output zero-fill (189MB, mandatory: d_out is poisoned) runs as two float4
// fill kernels on a side stream, overlapped with the conv chain, joined
// before the atomic scatter into the output.
// ---------------------------------------------------------------------------

namespace {
constexpr int kB  = 2;
constexpr int kDZ = 41, kHY = 400, kWX = 352;
constexpr int kGD = kDZ + 2, kGH = kHY + 2, kGW = kWX + 2;
constexpr int kN  = 40000;
constexpr int kDO = 21, kHO = 200, kWO = 176;
constexpr int kGridCells = kB * kGD * kGH * kGW;  // 12,238,488
}

__device__ unsigned short g_grid[kGridCells];     // 24.5 MB, idx+1 (0 empty)
__device__ int   g_cnt[kN];
__device__ int   g_list[kN * 27];                 // packed (k<<16)|idx
__device__ __align__(16) float g_x1[kN * 16];
__device__ __align__(16) float g_x2[kN * 16];

__device__ __forceinline__ int cell_of(int4 c, int dk, int dy, int dx) {
    return ((c.x * kGD + c.y + dk) * kGH + c.z + dy) * kGW + c.w + dx;
}

// ---------------------------------------------------------------------------
__global__ void k_zero(float4* __restrict__ p, int n4) {
    int stride = gridDim.x * blockDim.x;
    for (int i = blockIdx.x * blockDim.x + threadIdx.x; i < n4; i += stride)
        p[i] = make_float4(0.f, 0.f, 0.f, 0.f);
}

__global__ void k_scatter(const int4* __restrict__ coors) {
    int n = blockIdx.x * blockDim.x + threadIdx.x;
    if (n >= kN) return;
    int4 c = __ldg(&coors[n]);
    g_grid[cell_of(c, 1, 1, 1)] = (unsigned short)(n + 1);
}

// ---------------------------------------------------------------------------
// conv1 (128->16, relu) fused with neighbor-list construction.
__global__ void k_conv1(const float* __restrict__ feat,
                        const int4* __restrict__ coors,
                        const float* __restrict__ W1) {
    int n    = blockIdx.x * (blockDim.x >> 5) + (threadIdx.x >> 5);
    int lane = threadIdx.x & 31;
    if (n >= kN) return;

    int4 c = __ldg(&coors[n]);

    int v = -1;
    if (lane < 27) {
        int dk = lane / 9, dy = (lane / 3) % 3, dx = lane % 3;
        v = (int)g_grid[cell_of(c, dk, dy, dx)] - 1;
    }
    unsigned ball = __ballot_sync(0xffffffffu, v >= 0);
    int pre = __popc(ball & ((1u << lane) - 1));
    if (v >= 0) g_list[n * 27 + pre] = (lane << 16) | v;
    if (lane == 0) g_cnt[n] = __popc(ball);

    float4 a0 = make_float4(0,0,0,0), a1 = a0, a2 = a0, a3 = a0;
    const float4* fv = reinterpret_cast<const float4*>(feat);
    const float4* wv = reinterpret_cast<const float4*>(W1);

    for (unsigned m = ball; m; m &= m - 1) {
        int k   = __ffs(m) - 1;
        int idx = __shfl_sync(0xffffffffu, v, k);
        float4 f = __ldcg(&fv[idx * 32 + lane]);
        const float4* wk = &wv[(k * 128 + lane * 4) * 4];
        float4 w;
        w = __ldg(wk + 0);  a0.x+=f.x*w.x; a0.y+=f.x*w.y; a0.z+=f.x*w.z; a0.w+=f.x*w.w;
        w = __ldg(wk + 1);  a1.x+=f.x*w.x; a1.y+=f.x*w.y; a1.z+=f.x*w.z; a1.w+=f.x*w.w;
        w = __ldg(wk + 2);  a2.x+=f.x*w.x; a2.y+=f.x*w.y; a2.z+=f.x*w.z; a2.w+=f.x*w.w;
        w = __ldg(wk + 3);  a3.x+=f.x*w.x; a3.y+=f.x*w.y; a3.z+=f.x*w.z; a3.w+=f.x*w.w;
        w = __ldg(wk + 4);  a0.x+=f.y*w.x; a0.y+=f.y*w.y; a0.z+=f.y*w.z; a0.w+=f.y*w.w;
        w = __ldg(wk + 5);  a1.x+=f.y*w.x; a1.y+=f.y*w.y; a1.z+=f.y*w.z; a1.w+=f.y*w.w;
        w = __ldg(wk + 6);  a2.x+=f.y*w.x; a2.y+=f.y*w.y; a2.z+=f.y*w.z; a2.w+=f.y*w.w;
        w = __ldg(wk + 7);  a3.x+=f.y*w.x; a3.y+=f.y*w.y; a3.z+=f.y*w.z; a3.w+=f.y*w.w;
        w = __ldg(wk + 8);  a0.x+=f.z*w.x; a0.y+=f.z*w.y; a0.z+=f.z*w.z; a0.w+=f.z*w.w;
        w = __ldg(wk + 9);  a1.x+=f.z*w.x; a1.y+=f.z*w.y; a1.z+=f.z*w.z; a1.w+=f.z*w.w;
        w = __ldg(wk + 10); a2.x+=f.z*w.x; a2.y+=f.z*w.y; a2.z+=f.z*w.z; a2.w+=f.z*w.w;
        w = __ldg(wk + 11); a3.x+=f.z*w.x; a3.y+=f.z*w.y; a3.z+=f.z*w.z; a3.w+=f.z*w.w;
        w = __ldg(wk + 12); a0.x+=f.w*w.x; a0.y+=f.w*w.y; a0.z+=f.w*w.z; a0.w+=f.w*w.w;
        w = __ldg(wk + 13); a1.x+=f.w*w.x; a1.y+=f.w*w.y; a1.z+=f.w*w.z; a1.w+=f.w*w.w;
        w = __ldg(wk + 14); a2.x+=f.w*w.x; a2.y+=f.w*w.y; a2.z+=f.w*w.z; a2.w+=f.w*w.w;
        w = __ldg(wk + 15); a3.x+=f.w*w.x; a3.y+=f.w*w.y; a3.z+=f.w*w.z; a3.w+=f.w*w.w;
    }

    float vals[16] = {a0.x,a0.y,a0.z,a0.w, a1.x,a1.y,a1.z,a1.w,
                      a2.x,a2.y,a2.z,a2.w, a3.x,a3.y,a3.z,a3.w};
    float res = 0.f;
    #pragma unroll
    for (int d = 0; d < 16; d++) {
        float t = vals[d];
        t += __shfl_xor_sync(0xffffffffu, t, 16);
        t += __shfl_xor_sync(0xffffffffu, t, 8);
        t += __shfl_xor_sync(0xffffffffu, t, 4);
        t += __shfl_xor_sync(0xffffffffu, t, 2);
        t += __shfl_xor_sync(0xffffffffu, t, 1);
        if (lane == d) res = t;
    }
    if (lane < 16) g_x1[n * 16 + lane] = fmaxf(res, 0.f);
}

// ---------------------------------------------------------------------------
// conv2 (16->16, relu): 16 lanes per point, lane = output channel.
// Also clears this point's grid cell (conv1 was the last grid reader).
__global__ void k_conv2(const float* __restrict__ W2,
                        const int4* __restrict__ coors) {
    int t = blockIdx.x * blockDim.x + threadIdx.x;
    int n = t >> 4;
    int d = t & 15;
    if (n >= kN) return;

    int cnt = g_cnt[n];
    float acc = 0.f;
    for (int j = 0; j < cnt; j++) {
        int p   = g_list[n * 27 + j];
        int idx = p & 0xffff;
        int k   = p >> 16;
        const float* xr = &g_x1[idx * 16];
        const float* wr = &W2[k * 256 + d];
        #pragma unroll
        for (int cc = 0; cc < 16; cc++)
            acc += xr[cc] * __ldg(&wr[cc * 16]);
    }
    g_x2[n * 16 + d] = fmaxf(acc, 0.f);

    if (d == 0) {                      // one lane per point clears the grid
        int4 c = __ldg(&coors[n]);
        g_grid[cell_of(c, 1, 1, 1)] = 0;
    }
}

// ---------------------------------------------------------------------------
// conv3 (16->32) + strided scatter. Warp per point, lane = output channel.
__global__ void k_conv3_scatter(const int4* __restrict__ coors,
                                const float* __restrict__ W3,
                                float* __restrict__ out) {
    int n    = blockIdx.x * (blockDim.x >> 5) + (threadIdx.x >> 5);
    int lane = threadIdx.x & 31;
    if (n >= kN) return;

    int4 c = __ldg(&coors[n]);
    float xs[16];
    #pragma unroll
    for (int cc = 0; cc < 16; cc++) xs[cc] = g_x2[n * 16 + cc];

    for (int dk = 0; dk < 3; dk++) {
        int oz = c.y + 1 - dk;
        if (oz < 0 || (oz & 1)) continue;
        int pz = oz >> 1;
        if (pz >= kDO) continue;
        for (int dy = 0; dy < 3; dy++) {
            int oy = c.z + 1 - dy;
            if (oy < 0 || (oy & 1)) continue;
            int py = oy >> 1;
            if (py >= kHO) continue;
            for (int dx = 0; dx < 3; dx++) {
                int ox = c.w + 1 - dx;
                if (ox < 0 || (ox & 1)) continue;
                int px = ox >> 1;
                if (px >= kWO) continue;
                int k    = dk * 9 + dy * 3 + dx;
                int base = ((c.x * kDO + pz) * kHO + py) * kWO + px;
                float v = 0.f;
                #pragma unroll
                for (int cc = 0; cc < 16; cc++)
                    v += xs[cc] * __ldg(&W3[(k * 16 + cc) * 32 + lane]);
                atomicAdd(&out[base * 32 + lane], v);
            }
        }
    }
}

// Idempotent relu over exactly the touched voxels (duplicates benign).
__global__ void k_relu_touched(const int4* __restrict__ coors,
                               float* __restrict__ out) {
    int n    = blockIdx.x * (blockDim.x >> 5) + (threadIdx.x >> 5);
    int lane = threadIdx.x & 31;
    if (n >= kN) return;

    int4 c = __ldg(&coors[n]);
    for (int dk = 0; dk < 3; dk++) {
        int oz = c.y + 1 - dk;
        if (oz < 0 || (oz & 1)) continue;
        int pz = oz >> 1;
        if (pz >= kDO) continue;
        for (int dy = 0; dy < 3; dy++) {
            int oy = c.z + 1 - dy;
            if (oy < 0 || (oy & 1)) continue;
            int py = oy >> 1;
            if (py >= kHO) continue;
            for (int dx = 0; dx < 3; dx++) {
                int ox = c.w + 1 - dx;
                if (ox < 0 || (ox & 1)) continue;
                int px = ox >> 1;
                if (px >= kWO) continue;
                int base = ((c.x * kDO + pz) * kHO + py) * kWO + px;
                int o = base * 32 + lane;
                out[o] = fmaxf(out[o], 0.f);
            }
        }
    }
}

// ---------------------------------------------------------------------------
extern "C" void kernel_launch(void* const* d_in, const int* in_sizes, int n_in,
                              void* d_out, int out_size) {
    const float* feat  = (const float*)d_in[0];
    const int4*  coors = (const int4*) d_in[1];
    const float* W1    = (const float*)d_in[2];
    const float* W2    = (const float*)d_in[3];
    const float* W3    = (const float*)d_in[4];
    float*       out   = (float*)d_out;
    (void)in_sizes; (void)n_in;

    static cudaStream_t side = nullptr;
    static cudaEvent_t  efork = nullptr, ejoin = nullptr;
    if (!side) {
        cudaStreamCreateWithFlags(&side, cudaStreamNonBlocking);
        cudaEventCreateWithFlags(&efork, cudaEventDisableTiming);
        cudaEventCreateWithFlags(&ejoin, cudaEventDisableTiming);
    }

    int n4 = out_size / 4;            // 11,827,200 float4s
    int h1 = n4 / 2, h2 = n4 - h1;

    // Fork: zero the 189MB output on the side stream (two kernels),
    // overlapped with the conv chain; join before the atomic scatter.
    cudaEventRecord(efork, 0);
    cudaStreamWaitEvent(side, efork, 0);
    k_zero<<<2048, 256, 0, side>>>((float4*)out, h1);                 // launch 1
    k_zero<<<2048, 256, 0, side>>>((float4*)out + h1, h2);            // launch 2
    cudaEventRecord(ejoin, side);

    k_scatter <<<(kN + 255) / 256, 256>>>(coors);                     // launch 3
    k_conv1   <<<(kN + 7) / 8, 256>>>(feat, coors, W1);               // launch 4 (profiled)
    k_conv2   <<<(kN * 16 + 255) / 256, 256>>>(W2, coors);            // launch 5

    cudaStreamWaitEvent(0, ejoin, 0);
    k_conv3_scatter <<<(kN + 7) / 8, 256>>>(coors, W3, out);          // launch 6
    k_relu_touched  <<<(kN + 7) / 8, 256>>>(coors, out);              // launch 7
}

// round 5
// speedup vs baseline: 1.9427x; 1.9427x over previous
#include <cuda_runtime.h>

// ---------------------------------------------------------------------------
// SpMiddleFHD. Sparsity insight: 0.355% occupancy => avg non-self neighbors
// ~0.09/point (~3.7K pairs total). Submanifold convs = dense self-term GEMV
// + tiny sparse pair corrections (shared pair list for conv1/conv2).
// Output pass: atomic scatter + fused relu/clear. 189MB output zero-fill on a
// low-footprint side stream (2 blocks/SM), joined before the scatter.
// Grid hash: idx+1 in uint16, zero-init invariant restored in k_dense2.
// ---------------------------------------------------------------------------

namespace {
constexpr int kB  = 2;
constexpr int kDZ = 41, kHY = 400, kWX = 352;
constexpr int kGD = kDZ + 2, kGH = kHY + 2, kGW = kWX + 2;
constexpr int kN  = 40000;
constexpr int kDO = 21, kHO = 200, kWO = 176;
constexpr int kGridCells = kB * kGD * kGH * kGW;  // 12,238,488
constexpr int kMaxPairs  = kN * 27;
}

__device__ unsigned short g_grid[kGridCells];     // idx+1 (0 empty)
__device__ int  g_np;                             // pair counter
__device__ int2 g_pairs[kMaxPairs];               // {n, (k<<16)|idx}
__device__ __align__(16) float g_x1[kN * 16];     // pre-relu conv1 out
__device__ __align__(16) float g_x2[kN * 16];     // pre-relu conv2 out

__device__ __forceinline__ int cell_of(int4 c) {
    return ((c.x * kGD + c.y + 1) * kGH + c.z + 1) * kGW + c.w + 1;
}

// ---------------------------------------------------------------------------
__global__ void k_zero(float4* __restrict__ p, int n4) {
    int stride = gridDim.x * blockDim.x;
    for (int i = blockIdx.x * blockDim.x + threadIdx.x; i < n4; i += stride)
        p[i] = make_float4(0.f, 0.f, 0.f, 0.f);
}

__global__ void k_scatter(const int4* __restrict__ coors) {
    int n = blockIdx.x * blockDim.x + threadIdx.x;
    if (n == 0) g_np = 0;
    if (n >= kN) return;
    int4 c = __ldg(&coors[n]);
    g_grid[cell_of(c)] = (unsigned short)(n + 1);
}

// Warp per point: probe 27 cells, compact non-self valid pairs globally.
__global__ void k_pairs_build(const int4* __restrict__ coors) {
    int n    = blockIdx.x * (blockDim.x >> 5) + (threadIdx.x >> 5);
    int lane = threadIdx.x & 31;
    if (n >= kN) return;
    int4 c = __ldg(&coors[n]);

    int v = -1;
    if (lane < 27) {
        int dk = lane / 9, dy = (lane / 3) % 3, dx = lane % 3;
        v = (int)g_grid[((c.x * kGD + c.y + dk) * kGH + c.z + dy) * kGW
                        + c.w + dx] - 1;
    }
    unsigned mask = __ballot_sync(0xffffffffu, v >= 0) & ~(1u << 13);
    int cnt = __popc(mask);
    int base = 0;
    if (cnt) {
        if (lane == 0) base = atomicAdd(&g_np, cnt);
        base = __shfl_sync(0xffffffffu, base, 0);
        if ((mask >> lane) & 1) {
            int pre = __popc(mask & ((1u << lane) - 1));
            g_pairs[base + pre] = make_int2(n, (lane << 16) | v);
        }
    }
}

// ---------------------------------------------------------------------------
// Dense conv1 self-term: x1[n] = feat[n] . W1[k=13]  (pre-relu store).
// Lane mapping: dq = lane&3 (output quarter), cg = lane>>2 (16-channel group).
// Reduce over cg with 3 xor-shuffle rounds (12 shuffles total).
__global__ void k_dense1(const float4* __restrict__ fv,
                         const float4* __restrict__ w1v) {
    int n    = blockIdx.x * (blockDim.x >> 5) + (threadIdx.x >> 5);
    int lane = threadIdx.x & 31;
    if (n >= kN) return;
    int dq = lane & 3, cg = lane >> 2;

    float4 f[4];
    #pragma unroll
    for (int q = 0; q < 4; q++) f[q] = __ldcg(&fv[n * 32 + cg * 4 + q]);

    float4 acc = make_float4(0.f, 0.f, 0.f, 0.f);
    const float4* wb = &w1v[13 * 512 + dq];
    #pragma unroll
    for (int q = 0; q < 4; q++) {
        float fs[4] = {f[q].x, f[q].y, f[q].z, f[q].w};
        #pragma unroll
        for (int j = 0; j < 4; j++) {
            int c = cg * 16 + q * 4 + j;
            float4 w = __ldg(&wb[c * 4]);
            acc.x += fs[j] * w.x; acc.y += fs[j] * w.y;
            acc.z += fs[j] * w.z; acc.w += fs[j] * w.w;
        }
    }
    #pragma unroll
    for (int o = 4; o < 32; o <<= 1) {
        acc.x += __shfl_xor_sync(0xffffffffu, acc.x, o);
        acc.y += __shfl_xor_sync(0xffffffffu, acc.y, o);
        acc.z += __shfl_xor_sync(0xffffffffu, acc.z, o);
        acc.w += __shfl_xor_sync(0xffffffffu, acc.w, o);
    }
    if (cg == 0)
        reinterpret_cast<float4*>(g_x1)[n * 4 + dq] = acc;
}

// Sparse conv1 corrections: x1[n] += feat[idx] . W1[k], via atomics.
__global__ void k_pairs1(const float4* __restrict__ fv,
                         const float4* __restrict__ w1v) {
    int wflat  = blockIdx.x * (blockDim.x >> 5) + (threadIdx.x >> 5);
    int nwarps = gridDim.x * (blockDim.x >> 5);
    int lane   = threadIdx.x & 31;
    int dq = lane & 3, cg = lane >> 2;
    int np = g_np;

    for (int p = wflat; p < np; p += nwarps) {
        int2 pr = g_pairs[p];
        int n = pr.x, k = pr.y >> 16, idx = pr.y & 0xffff;

        float4 f[4];
        #pragma unroll
        for (int q = 0; q < 4; q++) f[q] = __ldcg(&fv[idx * 32 + cg * 4 + q]);

        float4 acc = make_float4(0.f, 0.f, 0.f, 0.f);
        const float4* wb = &w1v[k * 512 + dq];
        #pragma unroll
        for (int q = 0; q < 4; q++) {
            float fs[4] = {f[q].x, f[q].y, f[q].z, f[q].w};
            #pragma unroll
            for (int j = 0; j < 4; j++) {
                int c = cg * 16 + q * 4 + j;
                float4 w = __ldg(&wb[c * 4]);
                acc.x += fs[j] * w.x; acc.y += fs[j] * w.y;
                acc.z += fs[j] * w.z; acc.w += fs[j] * w.w;
            }
        }
        #pragma unroll
        for (int o = 4; o < 32; o <<= 1) {
            acc.x += __shfl_xor_sync(0xffffffffu, acc.x, o);
            acc.y += __shfl_xor_sync(0xffffffffu, acc.y, o);
            acc.z += __shfl_xor_sync(0xffffffffu, acc.z, o);
            acc.w += __shfl_xor_sync(0xffffffffu, acc.w, o);
        }
        if (cg == 0) {
            float* dst = &g_x1[n * 16 + dq * 4];
            atomicAdd(dst + 0, acc.x); atomicAdd(dst + 1, acc.y);
            atomicAdd(dst + 2, acc.z); atomicAdd(dst + 3, acc.w);
        }
    }
}

// ---------------------------------------------------------------------------
// Dense conv2 self-term: x2[n][d] = sum_c relu(x1[n][c]) * W2[13][c][d].
// 16 lanes per point, lane = d. Also clears this point's grid cell.
__global__ void k_dense2(const float* __restrict__ W2,
                         const int4* __restrict__ coors) {
    int t = blockIdx.x * blockDim.x + threadIdx.x;
    int n = t >> 4, d = t & 15;
    if (n >= kN) return;

    const float* xr = &g_x1[n * 16];
    const float* wr = &W2[13 * 256 + d];
    float acc = 0.f;
    #pragma unroll
    for (int cc = 0; cc < 16; cc++)
        acc += fmaxf(xr[cc], 0.f) * __ldg(&wr[cc * 16]);
    g_x2[n * 16 + d] = acc;

    if (d == 0) {
        int4 c = __ldg(&coors[n]);
        g_grid[cell_of(c)] = 0;
    }
}

// Sparse conv2 corrections: 2 pairs per warp (16 lanes each).
__global__ void k_pairs2(const float* __restrict__ W2) {
    int wflat  = blockIdx.x * (blockDim.x >> 5) + (threadIdx.x >> 5);
    int nwarps = gridDim.x * (blockDim.x >> 5);
    int lane = threadIdx.x & 31;
    int h = lane >> 4, d = lane & 15;
    int np = g_np;

    for (int p0 = wflat * 2; p0 < np; p0 += nwarps * 2) {
        int p = p0 + h;
        if (p >= np) continue;
        int2 pr = g_pairs[p];
        int n = pr.x, k = pr.y >> 16, idx = pr.y & 0xffff;
        const float* xr = &g_x1[idx * 16];
        const float* wr = &W2[k * 256 + d];
        float acc = 0.f;
        #pragma unroll
        for (int cc = 0; cc < 16; cc++)
            acc += fmaxf(xr[cc], 0.f) * __ldg(&wr[cc * 16]);
        atomicAdd(&g_x2[n * 16 + d], acc);
    }
}

// ---------------------------------------------------------------------------
// conv3 (16->32) + strided scatter. Warp per (n, dk); lane = output channel.
__global__ void k_conv3(const int4* __restrict__ coors,
                        const float* __restrict__ W3,
                        float* __restrict__ out) {
    int n    = blockIdx.x * (blockDim.x >> 5) + (threadIdx.x >> 5);
    int lane = threadIdx.x & 31;
    int dk   = blockIdx.y;
    if (n >= kN) return;

    int4 c = __ldg(&coors[n]);
    int oz = c.y + 1 - dk;
    if (oz < 0 || (oz & 1)) return;
    int pz = oz >> 1;
    if (pz >= kDO) return;

    const float4* x2v = reinterpret_cast<const float4*>(&g_x2[n * 16]);
    float xs[16];
    #pragma unroll
    for (int q = 0; q < 4; q++) {
        float4 v = x2v[q];
        xs[q*4+0] = fmaxf(v.x, 0.f); xs[q*4+1] = fmaxf(v.y, 0.f);
        xs[q*4+2] = fmaxf(v.z, 0.f); xs[q*4+3] = fmaxf(v.w, 0.f);
    }

    for (int dy = 0; dy < 3; dy++) {
        int oy = c.z + 1 - dy;
        if (oy < 0 || (oy & 1)) continue;
        int py = oy >> 1;
        if (py >= kHO) continue;
        for (int dx = 0; dx < 3; dx++) {
            int ox = c.w + 1 - dx;
            if (ox < 0 || (ox & 1)) continue;
            int px = ox >> 1;
            if (px >= kWO) continue;
            int k    = dk * 9 + dy * 3 + dx;
            int base = ((c.x * kDO + pz) * kHO + py) * kWO + px;
            float v = 0.f;
            #pragma unroll
            for (int cc = 0; cc < 16; cc++)
                v += xs[cc] * __ldg(&W3[(k * 16 + cc) * 32 + lane]);
            atomicAdd(&out[base * 32 + lane], v);
        }
    }
}

// Idempotent relu over touched voxels, warp per (n, dk).
__global__ void k_relu_touched(const int4* __restrict__ coors,
                               float* __restrict__ out) {
    int n    = blockIdx.x * (blockDim.x >> 5) + (threadIdx.x >> 5);
    int lane = threadIdx.x & 31;
    int dk   = blockIdx.y;
    if (n >= kN) return;

    int4 c = __ldg(&coors[n]);
    int oz = c.y + 1 - dk;
    if (oz < 0 || (oz & 1)) return;
    int pz = oz >> 1;
    if (pz >= kDO) return;

    for (int dy = 0; dy < 3; dy++) {
        int oy = c.z + 1 - dy;
        if (oy < 0 || (oy & 1)) continue;
        int py = oy >> 1;
        if (py >= kHO) continue;
        for (int dx = 0; dx < 3; dx++) {
            int ox = c.w + 1 - dx;
            if (ox < 0 || (ox & 1)) continue;
            int px = ox >> 1;
            if (px >= kWO) continue;
            int base = ((c.x * kDO + pz) * kHO + py) * kWO + px;
            int o = base * 32 + lane;
            out[o] = fmaxf(out[o], 0.f);
        }
    }
}

// ---------------------------------------------------------------------------
extern "C" void kernel_launch(void* const* d_in, const int* in_sizes, int n_in,
                              void* d_out, int out_size) {
    const float* feat  = (const float*)d_in[0];
    const int4*  coors = (const int4*) d_in[1];
    const float* W1    = (const float*)d_in[2];
    const float* W2    = (const float*)d_in[3];
    const float* W3    = (const float*)d_in[4];
    float*       out   = (float*)d_out;
    (void)in_sizes; (void)n_in;

    static cudaStream_t side = nullptr;
    static cudaEvent_t  efork = nullptr, ejoin = nullptr;
    if (!side) {
        cudaStreamCreateWithFlags(&side, cudaStreamNonBlocking);
        cudaEventCreateWithFlags(&efork, cudaEventDisableTiming);
        cudaEventCreateWithFlags(&ejoin, cudaEventDisableTiming);
    }

    // Side stream: zero 189MB output with a small SM footprint (2 blocks/SM)
    // so the main-chain kernels keep their issue slots.
    cudaEventRecord(efork, 0);
    cudaStreamWaitEvent(side, efork, 0);
    k_zero<<<296, 256, 0, side>>>((float4*)out, out_size / 4);
    cudaEventRecord(ejoin, side);

    k_scatter     <<<(kN + 255) / 256, 256>>>(coors);
    k_pairs_build <<<(kN + 7) / 8, 256>>>(coors);
    k_dense1      <<<(kN + 7) / 8, 256>>>((const float4*)feat,
                                          (const float4*)W1);
    k_pairs1      <<<128, 256>>>((const float4*)feat, (const float4*)W1);
    k_dense2      <<<(kN * 16 + 255) / 256, 256>>>(W2, coors);
    k_pairs2      <<<128, 256>>>(W2);

    cudaStreamWaitEvent(0, ejoin, 0);
    dim3 g3((kN + 7) / 8, 3);
    k_conv3        <<<g3, 256>>>(coors, W3, out);
    k_relu_touched <<<g3, 256>>>(coors, out);
}

// round 6
// speedup vs baseline: 2.0915x; 1.0766x over previous
#include <cuda_runtime.h>

// ---------------------------------------------------------------------------
// SpMiddleFHD. Sparsity: 0.355% occupancy => ~3.7K non-self pairs among 40000
// points. Submanifold convs = dense self-term GEMV + tiny sparse corrections.
// Output: atomic scatter + idempotent relu pass. 189MB zero-fill overlapped
// on a side stream (4 blocks/SM), joined before the scatter.
// Grid hash: idx+1 in uint16, zero-invariant restored in k_dense2.
// ---------------------------------------------------------------------------

namespace {
constexpr int kB  = 2;
constexpr int kDZ = 41, kHY = 400, kWX = 352;
constexpr int kGD = kDZ + 2, kGH = kHY + 2, kGW = kWX + 2;
constexpr int kN  = 40000;
constexpr int kDO = 21, kHO = 200, kWO = 176;
constexpr int kGridCells = kB * kGD * kGH * kGW;  // 12,238,488
constexpr int kMaxPairs  = kN * 27;
}

__device__ unsigned short g_grid[kGridCells];     // idx+1 (0 empty)
__device__ int  g_np;                             // pair counter
__device__ int2 g_pairs[kMaxPairs];               // {n, (k<<16)|idx}
__device__ __align__(16) float g_x1[kN * 16];     // pre-relu conv1 out
__device__ __align__(16) float g_x2[kN * 16];     // pre-relu conv2 out

__device__ __forceinline__ int cell_of(int4 c) {
    return ((c.x * kGD + c.y + 1) * kGH + c.z + 1) * kGW + c.w + 1;
}

// ---------------------------------------------------------------------------
__global__ void k_zero(float4* __restrict__ p, int n4) {
    // 4x unrolled grid-stride fill for MLP.
    int stride = gridDim.x * blockDim.x;
    int i = blockIdx.x * blockDim.x + threadIdx.x;
    float4 z = make_float4(0.f, 0.f, 0.f, 0.f);
    int i3 = i + 3 * stride;
    for (; i3 < n4; i = i3 + stride, i3 = i + 3 * stride) {
        p[i] = z; p[i + stride] = z; p[i + 2 * stride] = z; p[i3] = z;
    }
    for (; i < n4; i += stride) p[i] = z;
}

__global__ void k_scatter(const int4* __restrict__ coors) {
    int n = blockIdx.x * blockDim.x + threadIdx.x;
    if (n == 0) g_np = 0;
    if (n >= kN) return;
    int4 c = __ldg(&coors[n]);
    g_grid[cell_of(c)] = (unsigned short)(n + 1);
}

// Warp per point: probe 27 cells, compact non-self valid pairs globally.
__global__ void k_pairs_build(const int4* __restrict__ coors) {
    int n    = blockIdx.x * (blockDim.x >> 5) + (threadIdx.x >> 5);
    int lane = threadIdx.x & 31;
    if (n >= kN) return;
    int4 c = __ldg(&coors[n]);

    int v = -1;
    if (lane < 27) {
        int dk = lane / 9, dy = (lane / 3) % 3, dx = lane % 3;
        v = (int)g_grid[((c.x * kGD + c.y + dk) * kGH + c.z + dy) * kGW
                        + c.w + dx] - 1;
    }
    unsigned mask = __ballot_sync(0xffffffffu, v >= 0) & ~(1u << 13);
    int cnt = __popc(mask);
    int base = 0;
    if (cnt) {
        if (lane == 0) base = atomicAdd(&g_np, cnt);
        base = __shfl_sync(0xffffffffu, base, 0);
        if ((mask >> lane) & 1) {
            int pre = __popc(mask & ((1u << lane) - 1));
            g_pairs[base + pre] = make_int2(n, (lane << 16) | v);
        }
    }
}

// ---------------------------------------------------------------------------
// Dense conv1 self-term: x1[n] = feat[n] . W1[13]  (pre-relu store).
// 4 points per warp per W-load batch (amortizes W L1 wavefronts 4x).
// Lane mapping: dq = lane&3 (out quarter), cg = lane>>2 (16-ch group).
__global__ void k_dense1(const float4* __restrict__ fv,
                         const float4* __restrict__ w1v) {
    int w    = blockIdx.x * (blockDim.x >> 5) + (threadIdx.x >> 5);
    int lane = threadIdx.x & 31;
    int n0   = w * 4;
    if (n0 >= kN) return;
    int dq = lane & 3, cg = lane >> 2;

    float fs[4][16];
    #pragma unroll
    for (int p = 0; p < 4; p++) {
        #pragma unroll
        for (int q = 0; q < 4; q++) {
            float4 f = __ldcg(&fv[(n0 + p) * 32 + cg * 4 + q]);
            fs[p][q*4+0] = f.x; fs[p][q*4+1] = f.y;
            fs[p][q*4+2] = f.z; fs[p][q*4+3] = f.w;
        }
    }

    float4 acc[4];
    #pragma unroll
    for (int p = 0; p < 4; p++) acc[p] = make_float4(0.f, 0.f, 0.f, 0.f);

    const float4* wb = &w1v[13 * 512 + dq];
    #pragma unroll
    for (int e = 0; e < 16; e++) {
        int c = cg * 16 + e;
        float4 wv = __ldg(&wb[c * 4]);
        #pragma unroll
        for (int p = 0; p < 4; p++) {
            float f = fs[p][e];
            acc[p].x += f * wv.x; acc[p].y += f * wv.y;
            acc[p].z += f * wv.z; acc[p].w += f * wv.w;
        }
    }

    #pragma unroll
    for (int p = 0; p < 4; p++) {
        #pragma unroll
        for (int o = 4; o < 32; o <<= 1) {
            acc[p].x += __shfl_xor_sync(0xffffffffu, acc[p].x, o);
            acc[p].y += __shfl_xor_sync(0xffffffffu, acc[p].y, o);
            acc[p].z += __shfl_xor_sync(0xffffffffu, acc[p].z, o);
            acc[p].w += __shfl_xor_sync(0xffffffffu, acc[p].w, o);
        }
        if (cg == 0)
            reinterpret_cast<float4*>(g_x1)[(n0 + p) * 4 + dq] = acc[p];
    }
}

// Sparse conv1 corrections: x1[n] += feat[idx] . W1[k], via atomics.
__global__ void k_pairs1(const float4* __restrict__ fv,
                         const float4* __restrict__ w1v) {
    int wflat  = blockIdx.x * (blockDim.x >> 5) + (threadIdx.x >> 5);
    int nwarps = gridDim.x * (blockDim.x >> 5);
    int lane   = threadIdx.x & 31;
    int dq = lane & 3, cg = lane >> 2;
    int np = g_np;

    for (int p = wflat; p < np; p += nwarps) {
        int2 pr = g_pairs[p];
        int n = pr.x, k = pr.y >> 16, idx = pr.y & 0xffff;

        float fs[16];
        #pragma unroll
        for (int q = 0; q < 4; q++) {
            float4 f = __ldcg(&fv[idx * 32 + cg * 4 + q]);
            fs[q*4+0] = f.x; fs[q*4+1] = f.y; fs[q*4+2] = f.z; fs[q*4+3] = f.w;
        }

        float4 acc = make_float4(0.f, 0.f, 0.f, 0.f);
        const float4* wb = &w1v[k * 512 + dq];
        #pragma unroll
        for (int e = 0; e < 16; e++) {
            float4 wv = __ldg(&wb[(cg * 16 + e) * 4]);
            float f = fs[e];
            acc.x += f * wv.x; acc.y += f * wv.y;
            acc.z += f * wv.z; acc.w += f * wv.w;
        }
        #pragma unroll
        for (int o = 4; o < 32; o <<= 1) {
            acc.x += __shfl_xor_sync(0xffffffffu, acc.x, o);
            acc.y += __shfl_xor_sync(0xffffffffu, acc.y, o);
            acc.z += __shfl_xor_sync(0xffffffffu, acc.z, o);
            acc.w += __shfl_xor_sync(0xffffffffu, acc.w, o);
        }
        if (cg == 0) {
            float* dst = &g_x1[n * 16 + dq * 4];
            atomicAdd(dst + 0, acc.x); atomicAdd(dst + 1, acc.y);
            atomicAdd(dst + 2, acc.z); atomicAdd(dst + 3, acc.w);
        }
    }
}

// ---------------------------------------------------------------------------
// Dense conv2 self-term: x2[n][d] = sum_c relu(x1[n][c]) * W2[13][c][d].
// 16 lanes per point, lane = d. Also clears this point's grid cell.
__global__ void k_dense2(const float* __restrict__ W2,
                         const int4* __restrict__ coors) {
    int t = blockIdx.x * blockDim.x + threadIdx.x;
    int n = t >> 4, d = t & 15;
    if (n >= kN) return;

    const float* xr = &g_x1[n * 16];
    const float* wr = &W2[13 * 256 + d];
    float acc = 0.f;
    #pragma unroll
    for (int cc = 0; cc < 16; cc++)
        acc += fmaxf(xr[cc], 0.f) * __ldg(&wr[cc * 16]);
    g_x2[n * 16 + d] = acc;

    if (d == 0) {
        int4 c = __ldg(&coors[n]);
        g_grid[cell_of(c)] = 0;
    }
}

// Sparse conv2 corrections: 2 pairs per warp (16 lanes each).
__global__ void k_pairs2(const float* __restrict__ W2) {
    int wflat  = blockIdx.x * (blockDim.x >> 5) + (threadIdx.x >> 5);
    int nwarps = gridDim.x * (blockDim.x >> 5);
    int lane = threadIdx.x & 31;
    int h = lane >> 4, d = lane & 15;
    int np = g_np;

    for (int p0 = wflat * 2; p0 < np; p0 += nwarps * 2) {
        int p = p0 + h;
        if (p >= np) continue;
        int2 pr = g_pairs[p];
        int n = pr.x, k = pr.y >> 16, idx = pr.y & 0xffff;
        const float* xr = &g_x1[idx * 16];
        const float* wr = &W2[k * 256 + d];
        float acc = 0.f;
        #pragma unroll
        for (int cc = 0; cc < 16; cc++)
            acc += fmaxf(xr[cc], 0.f) * __ldg(&wr[cc * 16]);
        atomicAdd(&g_x2[n * 16 + d], acc);
    }
}

// ---------------------------------------------------------------------------
// conv3 (16->32) + strided scatter. Warp per (n, dk); lane = output channel.
__global__ void k_conv3(const int4* __restrict__ coors,
                        const float* __restrict__ W3,
                        float* __restrict__ out) {
    int n    = blockIdx.x * (blockDim.x >> 5) + (threadIdx.x >> 5);
    int lane = threadIdx.x & 31;
    int dk   = blockIdx.y;
    if (n >= kN) return;

    int4 c = __ldg(&coors[n]);
    int oz = c.y + 1 - dk;
    if (oz < 0 || (oz & 1)) return;
    int pz = oz >> 1;
    if (pz >= kDO) return;

    const float4* x2v = reinterpret_cast<const float4*>(&g_x2[n * 16]);
    float xs[16];
    #pragma unroll
    for (int q = 0; q < 4; q++) {
        float4 v = x2v[q];
        xs[q*4+0] = fmaxf(v.x, 0.f); xs[q*4+1] = fmaxf(v.y, 0.f);
        xs[q*4+2] = fmaxf(v.z, 0.f); xs[q*4+3] = fmaxf(v.w, 0.f);
    }

    for (int dy = 0; dy < 3; dy++) {
        int oy = c.z + 1 - dy;
        if (oy < 0 || (oy & 1)) continue;
        int py = oy >> 1;
        if (py >= kHO) continue;
        for (int dx = 0; dx < 3; dx++) {
            int ox = c.w + 1 - dx;
            if (ox < 0 || (ox & 1)) continue;
            int px = ox >> 1;
            if (px >= kWO) continue;
            int k    = dk * 9 + dy * 3 + dx;
            int base = ((c.x * kDO + pz) * kHO + py) * kWO + px;
            float v = 0.f;
            #pragma unroll
            for (int cc = 0; cc < 16; cc++)
                v += xs[cc] * __ldg(&W3[(k * 16 + cc) * 32 + lane]);
            atomicAdd(&out[base * 32 + lane], v);
        }
    }
}

// Idempotent relu over touched voxels, warp per (n, dk).
__global__ void k_relu_touched(const int4* __restrict__ coors,
                               float* __restrict__ out) {
    int n    = blockIdx.x * (blockDim.x >> 5) + (threadIdx.x >> 5);
    int lane = threadIdx.x & 31;
    int dk   = blockIdx.y;
    if (n >= kN) return;

    int4 c = __ldg(&coors[n]);
    int oz = c.y + 1 - dk;
    if (oz < 0 || (oz & 1)) return;
    int pz = oz >> 1;
    if (pz >= kDO) return;

    for (int dy = 0; dy < 3; dy++) {
        int oy = c.z + 1 - dy;
        if (oy < 0 || (oy & 1)) continue;
        int py = oy >> 1;
        if (py >= kHO) continue;
        for (int dx = 0; dx < 3; dx++) {
            int ox = c.w + 1 - dx;
            if (ox < 0 || (ox & 1)) continue;
            int px = ox >> 1;
            if (px >= kWO) continue;
            int base = ((c.x * kDO + pz) * kHO + py) * kWO + px;
            int o = base * 32 + lane;
            out[o] = fmaxf(out[o], 0.f);
        }
    }
}

// ---------------------------------------------------------------------------
extern "C" void kernel_launch(void* const* d_in, const int* in_sizes, int n_in,
                              void* d_out, int out_size) {
    const float* feat  = (const float*)d_in[0];
    const int4*  coors = (const int4*) d_in[1];
    const float* W1    = (const float*)d_in[2];
    const float* W2    = (const float*)d_in[3];
    const float* W3    = (const float*)d_in[4];
    float*       out   = (float*)d_out;
    (void)in_sizes; (void)n_in;

    static cudaStream_t side = nullptr;
    static cudaEvent_t  efork = nullptr, ejoin = nullptr;
    if (!side) {
        cudaStreamCreateWithFlags(&side, cudaStreamNonBlocking);
        cudaEventCreateWithFlags(&efork, cudaEventDisableTiming);
        cudaEventCreateWithFlags(&ejoin, cudaEventDisableTiming);
    }

    // Side stream: zero 189MB output (4 blocks/SM), overlapped with chain.
    cudaEventRecord(efork, 0);
    cudaStreamWaitEvent(side, efork, 0);
    k_zero<<<592, 256, 0, side>>>((float4*)out, out_size / 4);
    cudaEventRecord(ejoin, side);

    k_scatter     <<<(kN + 255) / 256, 256>>>(coors);
    k_pairs_build <<<(kN + 7) / 8, 256>>>(coors);
    k_dense1      <<<(kN / 4 + 7) / 8, 256>>>((const float4*)feat,
                                              (const float4*)W1);
    k_pairs1      <<<128, 256>>>((const float4*)feat, (const float4*)W1);
    k_dense2      <<<(kN * 16 + 255) / 256, 256>>>(W2, coors);
    k_pairs2      <<<128, 256>>>(W2);

    cudaStreamWaitEvent(0, ejoin, 0);
    dim3 g3((kN + 7) / 8, 3);
    k_conv3        <<<g3, 256>>>(coors, W3, out);
    k_relu_touched <<<g3, 256>>>(coors, out);
}